// round 15
// baseline (speedup 1.0000x reference)
#include <cuda_runtime.h>
#include <cuda_bf16.h>
#include <cstdint>

#define EMBED 100
#define BATCH 8192
#define MAT_FLOATS (EMBED * EMBED)
#define F4_PER_MAT 2500      // 100*100/4
#define NTHREADS   256
#define WARPS_CTA  8
#define GRID       592       // >=4 CTAs/SM -> single persistent wave
#define TOT_WARPS  (GRID * WARPS_CTA)   // 4736
#define FULL_N     78        // 78*32 = 2496 float4; tail = 4

__global__ __launch_bounds__(NTHREADS)
void matrix_skipgram_kernel(const int* __restrict__ X_argument,
                            const int* __restrict__ X_functor,
                            const int* __restrict__ X_context,
                            const float* __restrict__ noun_matrix,
                            const float* __restrict__ functor_table,
                            const float* __restrict__ context_table,
                            float* __restrict__ out)
{
    __shared__ alignas(16) float s_arg[WARPS_CTA][EMBED];  // 400B rows, 16B aligned
    __shared__ float s_ctx[WARPS_CTA][EMBED];

    const int w    = threadIdx.x >> 5;
    const int lane = threadIdx.x & 31;
    const int wg   = blockIdx.x * WARPS_CTA + w;

    const float4* __restrict__ a4 = reinterpret_cast<const float4*>(s_arg[w]);

    for (int b = wg; b < BATCH; b += TOT_WARPS) {
        // Stage this element's vectors (warp-local; 4 rounds of 32 lanes).
        {
            const float* av = noun_matrix   + (size_t)X_argument[b] * EMBED;
            const float* cv = context_table + (size_t)X_context[b]  * EMBED;
            #pragma unroll
            for (int i = lane; i < EMBED; i += 32) {
                s_arg[w][i] = av[i];
                s_ctx[w][i] = cv[i];
            }
        }
        const int f = X_functor[b];
        const float4* __restrict__ M =
            reinterpret_cast<const float4*>(functor_table + (size_t)f * MAT_FLOATS);
        __syncwarp();

        // Stream the matrix: 78 LDG.128 per lane, fully unrolled so ptxas
        // pipelines loads in rolling waves (no barriers, no drain points).
        float acc = 0.0f;
        #pragma unroll
        for (int n = 0; n < FULL_N; ++n) {
            const int k4 = lane + n * 32;          // < 2496
            const float4 m = __ldg(&M[k4]);
            const int i = k4 / 25;                 // row (ctx index)
            const int c = k4 - i * 25;             // float4 column
            const float4 a = a4[c];
            float dot = m.x * a.x + m.y * a.y + m.z * a.z + m.w * a.w;
            acc = fmaf(s_ctx[w][i], dot, acc);
        }
        if (lane < 4) {                            // tail: k4 = 2496..2499
            const int k4 = 2496 + lane;
            const float4 m = __ldg(&M[k4]);
            const int i = k4 / 25;
            const int c = k4 - i * 25;
            const float4 a = a4[c];
            float dot = m.x * a.x + m.y * a.y + m.z * a.z + m.w * a.w;
            acc = fmaf(s_ctx[w][i], dot, acc);
        }

        // Warp reduction, lane 0 stores.
        #pragma unroll
        for (int o = 16; o > 0; o >>= 1)
            acc += __shfl_xor_sync(0xFFFFFFFFu, acc, o);
        if (lane == 0)
            out[b] = acc;
        __syncwarp();   // all lanes done reading s_arg/s_ctx before restaging
    }
}

extern "C" void kernel_launch(void* const* d_in, const int* in_sizes, int n_in,
                              void* d_out, int out_size)
{
    const int*   X_argument    = (const int*)  d_in[0];
    const int*   X_functor     = (const int*)  d_in[1];
    const int*   X_context     = (const int*)  d_in[2];
    const float* noun_matrix   = (const float*)d_in[3];
    const float* functor_table = (const float*)d_in[4];
    const float* context_table = (const float*)d_in[5];
    float* out = (float*)d_out;

    matrix_skipgram_kernel<<<GRID, NTHREADS>>>(
        X_argument, X_functor, X_context,
        noun_matrix, functor_table, context_table, out);
}

// round 17
// speedup vs baseline: 1.1283x; 1.1283x over previous
#include <cuda_runtime.h>
#include <cuda_bf16.h>
#include <cstdint>

#define EMBED 100
#define BATCH 8192
#define BLK8_PER_MAT 1250   // 100*100 floats / 8
#define NTHREADS     256
#define ITERS8       5      // ceil(1250/256); iters 0..3 always in-bounds

// 32B non-coherent load with L2 evict_last (sm_103 requires .v4.b64 for this
// modifier). Returns two row-aligned float4s.
__device__ __forceinline__ void ldg_mat8(const float* p, float4& a, float4& b)
{
    unsigned long long q0, q1, q2, q3;
    asm("ld.global.nc.L2::evict_last.v4.b64 {%0,%1,%2,%3}, [%4];"
        : "=l"(q0), "=l"(q1), "=l"(q2), "=l"(q3) : "l"(p));
    a.x = __int_as_float((int)(q0));  a.y = __int_as_float((int)(q0 >> 32));
    a.z = __int_as_float((int)(q1));  a.w = __int_as_float((int)(q1 >> 32));
    b.x = __int_as_float((int)(q2));  b.y = __int_as_float((int)(q2 >> 32));
    b.z = __int_as_float((int)(q3));  b.w = __int_as_float((int)(q3 >> 32));
}

__global__ __launch_bounds__(NTHREADS)
void matrix_skipgram_kernel(const int* __restrict__ X_argument,
                            const int* __restrict__ X_functor,
                            const int* __restrict__ X_context,
                            const float* __restrict__ noun_matrix,
                            const float* __restrict__ functor_table,
                            const float* __restrict__ context_table,
                            float* __restrict__ out)
{
    const int b = blockIdx.x;
    const int t = threadIdx.x;

    __shared__ float s_arg[EMBED];
    __shared__ float s_ctx[EMBED];
    __shared__ float s_red[NTHREADS / 32];

    {
        const float* av = noun_matrix   + (size_t)X_argument[b] * EMBED;
        const float* cv = context_table + (size_t)X_context[b]  * EMBED;
        if (t < EMBED) {
            s_arg[t] = av[t];
            s_ctx[t] = cv[t];
        }
    }

    const float* __restrict__ M =
        functor_table + (size_t)X_functor[b] * (EMBED * EMBED);

    // Front-batched matrix stream: 5 independent 32B LDG per thread
    // (same 160B/thread in flight and same 40 data regs as the float4 version).
    const int k8_4  = t + 4 * NTHREADS;
    const bool v4   = (k8_4 < BLK8_PER_MAT);
    float4 ma[ITERS8], mb[ITERS8];
    #pragma unroll
    for (int it = 0; it < ITERS8 - 1; ++it)
        ldg_mat8(M + (t + it * NTHREADS) * 8, ma[it], mb[it]);
    ldg_mat8(M + (v4 ? k8_4 * 8 : 0), ma[ITERS8 - 1], mb[ITERS8 - 1]);

    __syncthreads();   // s_arg/s_ctx ready; matrix loads in flight

    float acc = 0.0f;
    #pragma unroll
    for (int it = 0; it < ITERS8; ++it) {
        const bool valid = (it < ITERS8 - 1) || v4;
        const int k8 = valid ? (t + it * NTHREADS) : 0;
        // First float4: float4-index 2*k8; second: 2*k8+1. Each lies in one row.
        const int e4a = 2 * k8,          e4b = 2 * k8 + 1;
        const int ia  = e4a / 25,        ib  = e4b / 25;
        const int ja  = (e4a - ia * 25) * 4;
        const int jb  = (e4b - ib * 25) * 4;
        float dota = ma[it].x * s_arg[ja]     + ma[it].y * s_arg[ja + 1]
                   + ma[it].z * s_arg[ja + 2] + ma[it].w * s_arg[ja + 3];
        float dotb = mb[it].x * s_arg[jb]     + mb[it].y * s_arg[jb + 1]
                   + mb[it].z * s_arg[jb + 2] + mb[it].w * s_arg[jb + 3];
        const float ca = valid ? s_ctx[ia] : 0.0f;
        const float cb = valid ? s_ctx[ib] : 0.0f;
        acc = fmaf(ca, dota, acc);
        acc = fmaf(cb, dotb, acc);
    }

    // Warp reduction
    #pragma unroll
    for (int o = 16; o > 0; o >>= 1)
        acc += __shfl_xor_sync(0xFFFFFFFFu, acc, o);

    if ((t & 31) == 0)
        s_red[t >> 5] = acc;
    __syncthreads();

    if (t < (NTHREADS / 32)) {
        acc = s_red[t];
        #pragma unroll
        for (int o = (NTHREADS / 64); o > 0; o >>= 1)
            acc += __shfl_xor_sync(0xFFu, acc, o);
        if (t == 0)
            out[b] = acc;
    }
}

extern "C" void kernel_launch(void* const* d_in, const int* in_sizes, int n_in,
                              void* d_out, int out_size)
{
    const int*   X_argument    = (const int*)  d_in[0];
    const int*   X_functor     = (const int*)  d_in[1];
    const int*   X_context     = (const int*)  d_in[2];
    const float* noun_matrix   = (const float*)d_in[3];
    const float* functor_table = (const float*)d_in[4];
    const float* context_table = (const float*)d_in[5];
    float* out = (float*)d_out;

    matrix_skipgram_kernel<<<BATCH, NTHREADS>>>(
        X_argument, X_functor, X_context,
        noun_matrix, functor_table, context_table, out);
}